// round 2
// baseline (speedup 1.0000x reference)
#include <cuda_runtime.h>
#include <math.h>

// ---------------- scratch (device globals; no runtime allocation) ----------------
__device__ float2 g_s3[16777216];   // [4][64][64][8][128]  (fwd L out / inv W out)
__device__ float2 g_s2[8388608];    // [4][64][32][8][128]  (fwd W out / inv H out)
__device__ float2 g_spec[4194304];  // [4][32][32][8][128]  truncated spectrum
__device__ float2 g_mlp[4194304];   // MLP output
__device__ float  g_W[8192];        // [4][8][16][16] folded weights
__device__ float  g_Bias[512];      // [4][8][16]     folded biases

// ---------------- twiddle tables ----------------
__constant__ float2 TW32[32] = {
  { 1.000000000f, 0.000000000f},{ 0.980785280f, 0.195090322f},{ 0.923879533f, 0.382683432f},{ 0.831469612f, 0.555570233f},
  { 0.707106781f, 0.707106781f},{ 0.555570233f, 0.831469612f},{ 0.382683432f, 0.923879533f},{ 0.195090322f, 0.980785280f},
  { 0.000000000f, 1.000000000f},{-0.195090322f, 0.980785280f},{-0.382683432f, 0.923879533f},{-0.555570233f, 0.831469612f},
  {-0.707106781f, 0.707106781f},{-0.831469612f, 0.555570233f},{-0.923879533f, 0.382683432f},{-0.980785280f, 0.195090322f},
  {-1.000000000f, 0.000000000f},{-0.980785280f,-0.195090322f},{-0.923879533f,-0.382683432f},{-0.831469612f,-0.555570233f},
  {-0.707106781f,-0.707106781f},{-0.555570233f,-0.831469612f},{-0.382683432f,-0.923879533f},{-0.195090322f,-0.980785280f},
  { 0.000000000f,-1.000000000f},{ 0.195090322f,-0.980785280f},{ 0.382683432f,-0.923879533f},{ 0.555570233f,-0.831469612f},
  { 0.707106781f,-0.707106781f},{ 0.831469612f,-0.555570233f},{ 0.923879533f,-0.382683432f},{ 0.980785280f,-0.195090322f}
};
__constant__ float2 TW64[64] = {
  { 1.000000000f, 0.000000000f},{ 0.995184727f, 0.098017140f},{ 0.980785280f, 0.195090322f},{ 0.956940336f, 0.290284677f},
  { 0.923879533f, 0.382683432f},{ 0.881921264f, 0.471396737f},{ 0.831469612f, 0.555570233f},{ 0.773010453f, 0.634393284f},
  { 0.707106781f, 0.707106781f},{ 0.634393284f, 0.773010453f},{ 0.555570233f, 0.831469612f},{ 0.471396737f, 0.881921264f},
  { 0.382683432f, 0.923879533f},{ 0.290284677f, 0.956940336f},{ 0.195090322f, 0.980785280f},{ 0.098017140f, 0.995184727f},
  { 0.000000000f, 1.000000000f},{-0.098017140f, 0.995184727f},{-0.195090322f, 0.980785280f},{-0.290284677f, 0.956940336f},
  {-0.382683432f, 0.923879533f},{-0.471396737f, 0.881921264f},{-0.555570233f, 0.831469612f},{-0.634393284f, 0.773010453f},
  {-0.707106781f, 0.707106781f},{-0.773010453f, 0.634393284f},{-0.831469612f, 0.555570233f},{-0.881921264f, 0.471396737f},
  {-0.923879533f, 0.382683432f},{-0.956940336f, 0.290284677f},{-0.980785280f, 0.195090322f},{-0.995184727f, 0.098017140f},
  {-1.000000000f, 0.000000000f},{-0.995184727f,-0.098017140f},{-0.980785280f,-0.195090322f},{-0.956940336f,-0.290284677f},
  {-0.923879533f,-0.382683432f},{-0.881921264f,-0.471396737f},{-0.831469612f,-0.555570233f},{-0.773010453f,-0.634393284f},
  {-0.707106781f,-0.707106781f},{-0.634393284f,-0.773010453f},{-0.555570233f,-0.831469612f},{-0.471396737f,-0.881921264f},
  {-0.382683432f,-0.923879533f},{-0.290284677f,-0.956940336f},{-0.195090322f,-0.980785280f},{-0.098017140f,-0.995184727f},
  { 0.000000000f,-1.000000000f},{ 0.098017140f,-0.995184727f},{ 0.195090322f,-0.980785280f},{ 0.290284677f,-0.956940336f},
  { 0.382683432f,-0.923879533f},{ 0.471396737f,-0.881921264f},{ 0.555570233f,-0.831469612f},{ 0.634393284f,-0.773010453f},
  { 0.707106781f,-0.707106781f},{ 0.773010453f,-0.634393284f},{ 0.831469612f,-0.555570233f},{ 0.881921264f,-0.471396737f},
  { 0.923879533f,-0.382683432f},{ 0.956940336f,-0.290284677f},{ 0.980785280f,-0.195090322f},{ 0.995184727f,-0.098017140f}
};

__device__ __forceinline__ float gelu_f(float v){
  return 0.5f*v*(1.0f+erff(v*0.7071067811865476f));
}

// ---------------- K0: fold HydraLoRA into dense per-block weights ----------------
// W[m][k] = base[m][k] + (1/32) * A[m][k] @ (sum_e ew[e] B[m][k][e])
// m: 0=W1R(w1[0],A1r,B1r) 1=W1I(w1[1],A1i,B1i) 2=W2R(w2[0],A2r,B2r) 3=W2I(w2[1],A2i,B2i)
__global__ void k_prep(const float* __restrict__ w1, const float* __restrict__ b1,
                       const float* __restrict__ w2, const float* __restrict__ b2,
                       const float* __restrict__ A1r, const float* __restrict__ B1r,
                       const float* __restrict__ A1i, const float* __restrict__ B1i,
                       const float* __restrict__ A2r, const float* __restrict__ B2r,
                       const float* __restrict__ A2i, const float* __restrict__ B2i,
                       const float* __restrict__ ew){
  int k  = blockIdx.x;        // block 0..7
  int io = threadIdx.x;       // 0..255
  int i = io >> 4, o = io & 15;
  float e0 = ew[0], e1 = ew[1], e2 = ew[2], e3 = ew[3];
  const float s = 0.03125f;   // ALPHA/R = 1/32
  const float* Ws[4] = { w1 + k*256, w1 + 2048 + k*256, w2 + k*256, w2 + 2048 + k*256 };
  const float* As[4] = { A1r + k*512, A1i + k*512, A2r + k*512, A2i + k*512 };
  const float* Bs[4] = { B1r + k*2048, B1i + k*2048, B2r + k*2048, B2i + k*2048 };
#pragma unroll
  for (int m = 0; m < 4; m++){
    const float* A  = As[m] + i*32;
    const float* Bb = Bs[m];
    float acc = 0.f;
    for (int r = 0; r < 32; r++){
      float bm = e0*Bb[r*16+o] + e1*Bb[512+r*16+o] + e2*Bb[1024+r*16+o] + e3*Bb[1536+r*16+o];
      acc = fmaf(A[r], bm, acc);
    }
    g_W[((m*8+k)*16+i)*16+o] = Ws[m][i*16+o] + s*acc;
  }
  if (io < 16){
    float b10 = b1[k*16+io], b11 = b1[128+k*16+io];
    float b20 = b2[k*16+io], b21 = b2[128+k*16+io];
    g_Bias[      k*16+io] = b10 - b11;
    g_Bias[128 + k*16+io] = b10 + b11;
    g_Bias[256 + k*16+io] = b20 - b21;
    g_Bias[384 + k*16+io] = b20 + b21;
  }
}

// ---------------- K1: forward rfft over L (32 -> 8 modes), e^{-i} ----------------
__global__ void k_fwd_l(const float* __restrict__ x){
  __shared__ float2 tw[32];
  if (threadIdx.x < 32) tw[threadIdx.x] = TW32[threadIdx.x];
  __syncthreads();
  int site = blockIdx.x;      // b*4096 + y*64 + xx
  int c = threadIdx.x;        // 0..127
  const float* xp = x + (size_t)site*4096 + c;
  float ar[8], ai[8];
#pragma unroll
  for (int l=0;l<8;l++){ ar[l]=0.f; ai[l]=0.f; }
#pragma unroll 4
  for (int t=0;t<32;t++){
    float v = xp[t*128];
#pragma unroll
    for (int l=0;l<8;l++){
      float2 w = tw[(t*l)&31];
      ar[l] = fmaf(v, w.x, ar[l]);
      ai[l] = fmaf(-v, w.y, ai[l]);
    }
  }
  const float s = 0.1767766952966369f; // 1/sqrt(32)
  float2* op = g_s3 + (size_t)site*1024 + c;
#pragma unroll
  for (int l=0;l<8;l++) op[l*128] = make_float2(ar[l]*s, ai[l]*s);
}

// ---------------- K2: forward DFT over W (64 -> 32 modes), e^{-i} ----------------
__global__ void k_fwd_w(){
  __shared__ float2 tw[64];
  if (threadIdx.x < 64) tw[threadIdx.x] = TW64[threadIdx.x];
  __syncthreads();
  int tid = blockIdx.x*blockDim.x + threadIdx.x;  // 262144 = (b*64+h)*8*128
  int c = tid & 127;
  int l = (tid>>7)&7;
  int bh = tid>>10;
  const float2* ip = g_s3 + (size_t)bh*65536 + l*128 + c;
  float ar[32], ai[32];
#pragma unroll
  for (int w=0;w<32;w++){ ar[w]=0.f; ai[w]=0.f; }
  for (int xx=0; xx<64; xx++){
    float2 v = ip[(size_t)xx*1024];
    int idx = 0;
#pragma unroll
    for (int w=0;w<32;w++){
      float2 t = tw[idx];
      ar[w] += v.x*t.x + v.y*t.y;
      ai[w] += v.y*t.x - v.x*t.y;
      idx = (idx + xx) & 63;
    }
  }
  float2* op = g_s2 + (size_t)bh*32768 + l*128 + c;
#pragma unroll
  for (int w=0;w<32;w++) op[(size_t)w*1024] = make_float2(ar[w]*0.125f, ai[w]*0.125f);
}

// ---------------- K3: forward DFT over H (64 -> 32 modes), e^{-i} ----------------
__global__ void k_fwd_h(){
  __shared__ float2 tw[64];
  if (threadIdx.x < 64) tw[threadIdx.x] = TW64[threadIdx.x];
  __syncthreads();
  int tid = blockIdx.x*blockDim.x + threadIdx.x;  // 131072
  int c = tid & 127;
  int l = (tid>>7)&7;
  int w = (tid>>10)&31;
  int b = tid>>15;
  const float2* ip = g_s2 + (size_t)b*2097152 + w*1024 + l*128 + c;
  float ar[32], ai[32];
#pragma unroll
  for (int h=0;h<32;h++){ ar[h]=0.f; ai[h]=0.f; }
  for (int y=0; y<64; y++){
    float2 v = ip[(size_t)y*32768];
    int idx = 0;
#pragma unroll
    for (int h=0;h<32;h++){
      float2 t = tw[idx];
      ar[h] += v.x*t.x + v.y*t.y;
      ai[h] += v.y*t.x - v.x*t.y;
      idx = (idx + y) & 63;
    }
  }
  float2* op = g_spec + (size_t)b*1048576 + w*1024 + l*128 + c;
#pragma unroll
  for (int h=0;h<32;h++) op[(size_t)h*32768] = make_float2(ar[h]*0.125f, ai[h]*0.125f);
}

// ---------------- K4: complex block-diagonal 2-layer MLP (LoRA folded) ----------------
__global__ void k_mlp(){
  __shared__ float sW[32*257];   // padded: bank-conflict-free for nb = lane&7
  __shared__ float sB[32*17];
  for (int i=threadIdx.x; i<8192; i+=256) sW[(i>>8)*257 + (i&255)] = g_W[i];
  for (int i=threadIdx.x; i<512;  i+=256) sB[(i>>4)*17  + (i&15) ] = g_Bias[i];
  __syncthreads();
  int tid = blockIdx.x*256 + threadIdx.x;   // 262144 = 32768 sites * 8 blocks
  int nb = tid & 7;
  int site = tid >> 3;
  const float2* ip = g_spec + (size_t)site*128 + nb*16;
  const float* W1R = sW + nb*257;
  const float* W1I = sW + (8+nb)*257;
  const float* W2R = sW + (16+nb)*257;
  const float* W2I = sW + (24+nb)*257;
  const float* B0 = sB + nb*17;
  const float* B1 = sB + (8+nb)*17;
  const float* B2 = sB + (16+nb)*17;
  const float* B3 = sB + (24+nb)*17;
  float xr[16], xi[16];
#pragma unroll
  for (int i=0;i<16;i++){ float2 v = ip[i]; xr[i]=v.x; xi[i]=v.y; }
  float pr[16], pi[16];
#pragma unroll
  for (int o=0;o<16;o++){ pr[o]=B0[o]; pi[o]=B1[o]; }
#pragma unroll
  for (int i=0;i<16;i++){
#pragma unroll
    for (int o=0;o<16;o++){
      float wr = W1R[i*16+o], wi = W1I[i*16+o];
      pr[o] += xr[i]*wr - xi[i]*wi;
      pi[o] += xi[i]*wr + xr[i]*wi;
    }
  }
#pragma unroll
  for (int o=0;o<16;o++){ pr[o]=gelu_f(pr[o]); pi[o]=gelu_f(pi[o]); }
  float qr[16], qi[16];
#pragma unroll
  for (int o=0;o<16;o++){ qr[o]=B2[o]; qi[o]=B3[o]; }
#pragma unroll
  for (int i=0;i<16;i++){
#pragma unroll
    for (int o=0;o<16;o++){
      float wr = W2R[i*16+o], wi = W2I[i*16+o];
      qr[o] += pr[i]*wr - pi[i]*wi;
      qi[o] += pi[i]*wr + pr[i]*wi;
    }
  }
  float2* op = g_mlp + (size_t)site*128 + nb*16;
#pragma unroll
  for (int o=0;o<16;o++) op[o] = make_float2(qr[o], qi[o]);
}

// ---------------- K5: inverse DFT over H (32 modes -> 64), e^{+i} ----------------
__global__ void k_inv_h(){
  __shared__ float2 tile[4096];  // [32 h][128 c]
  __shared__ float2 tw[64];
  if (threadIdx.x < 64) tw[threadIdx.x] = TW64[threadIdx.x];
  int bid = blockIdx.x;          // b*256 + w*8 + l   (1024 blocks)
  int l = bid&7, w = (bid>>3)&31, b = bid>>8;
  size_t base = (size_t)b*1048576 + w*1024 + l*128;
  for (int k=threadIdx.x; k<4096; k+=128){
    int h = k>>7, c = k&127;
    tile[k] = g_mlp[base + (size_t)h*32768 + c];
  }
  __syncthreads();
  int c = threadIdx.x;
  float2* op = g_s2 + (size_t)b*2097152 + w*1024 + l*128 + c;
  for (int y=0; y<64; y++){
    float ar=0.f, ai=0.f;
    int idx = 0;
#pragma unroll
    for (int h=0;h<32;h++){
      float2 v = tile[h*128+c];
      float2 t = tw[idx];
      ar += v.x*t.x - v.y*t.y;
      ai += v.y*t.x + v.x*t.y;
      idx = (idx + y) & 63;
    }
    op[(size_t)y*32768] = make_float2(ar*0.125f, ai*0.125f);
  }
}

// ---------------- K6: inverse DFT over W (32 modes -> 64), e^{+i} ----------------
__global__ void k_inv_w(){
  __shared__ float2 tile[4096];  // [32 w][128 c]
  __shared__ float2 tw[64];
  if (threadIdx.x < 64) tw[threadIdx.x] = TW64[threadIdx.x];
  int bid = blockIdx.x;          // b*512 + y*8 + l   (2048 blocks)
  int l = bid&7, y = (bid>>3)&63, b = bid>>9;
  size_t base = (size_t)b*2097152 + (size_t)y*32768 + l*128;
  for (int k=threadIdx.x; k<4096; k+=128){
    int w = k>>7, c = k&127;
    tile[k] = g_s2[base + w*1024 + c];
  }
  __syncthreads();
  int c = threadIdx.x;
  float2* op = g_s3 + (size_t)b*4194304 + (size_t)y*65536 + l*128 + c;
  for (int xx=0; xx<64; xx++){
    float ar=0.f, ai=0.f;
    int idx = 0;
#pragma unroll
    for (int w=0;w<32;w++){
      float2 v = tile[w*128+c];
      float2 t = tw[idx];
      ar += v.x*t.x - v.y*t.y;
      ai += v.y*t.x + v.x*t.y;
      idx = (idx + xx) & 63;
    }
    op[(size_t)xx*1024] = make_float2(ar*0.125f, ai*0.125f);
  }
}

// ---------------- K7: inverse rfft over L (8 modes -> 32 real) + residual ----------------
__global__ void k_inv_l(const float* __restrict__ xin, float* __restrict__ out){
  __shared__ float2 tw[32];
  if (threadIdx.x < 32) tw[threadIdx.x] = TW32[threadIdx.x];
  __syncthreads();
  int tid = blockIdx.x*blockDim.x + threadIdx.x;  // 2097152
  int c = tid & 127;
  int site = tid >> 7;                            // b*4096 + y*64 + x
  const float2* ip = g_s3 + (size_t)site*1024 + c;
  float Xr[8], Xi[8];
#pragma unroll
  for (int l=0;l<8;l++){ float2 v = ip[l*128]; Xr[l]=v.x; Xi[l]=v.y; }
#pragma unroll
  for (int l=1;l<8;l++){ Xr[l]*=2.f; Xi[l]*=2.f; }   // hermitian mirror (l=1..7); imag of DC ignored
  const float s = 0.1767766952966369f; // 1/sqrt(32)
  const float* rp = xin + (size_t)site*4096 + c;
  float* op = out + (size_t)site*4096 + c;
#pragma unroll 4
  for (int t=0;t<32;t++){
    float v = Xr[0];
#pragma unroll
    for (int l=1;l<8;l++){
      float2 w = tw[(l*t)&31];
      v += Xr[l]*w.x - Xi[l]*w.y;
    }
    op[t*128] = fmaf(v, s, rp[t*128]);
  }
}

// ---------------- launch ----------------
extern "C" void kernel_launch(void* const* d_in, const int* in_sizes, int n_in,
                              void* d_out, int out_size){
  (void)in_sizes; (void)n_in; (void)out_size;
  const float* x = (const float*)d_in[0];
  k_prep<<<8,256>>>((const float*)d_in[1], (const float*)d_in[2], (const float*)d_in[3],
                    (const float*)d_in[4], (const float*)d_in[5], (const float*)d_in[6],
                    (const float*)d_in[7], (const float*)d_in[8], (const float*)d_in[9],
                    (const float*)d_in[10], (const float*)d_in[11], (const float*)d_in[12],
                    (const float*)d_in[13]);
  k_fwd_l<<<16384,128>>>(x);
  k_fwd_w<<<1024,256>>>();
  k_fwd_h<<<512,256>>>();
  k_mlp<<<1024,256>>>();
  k_inv_h<<<1024,128>>>();
  k_inv_w<<<2048,128>>>();
  k_inv_l<<<16384,128>>>(x, (float*)d_out);
}

// round 3
// speedup vs baseline: 1.6634x; 1.6634x over previous
#include <cuda_runtime.h>
#include <math.h>

// ---------------- scratch (device globals; no runtime allocation) ----------------
__device__ __align__(16) float2 g_s3[16777216];   // [4][64][64][8][128]  (fwd L out / inv W out)
__device__ __align__(16) float2 g_s2[8388608];    // [4][64][32][8][128]  (fwd W out / inv H out)
__device__ __align__(16) float2 g_spec[4194304];  // [4][32][32][8][128]  truncated spectrum
__device__ __align__(16) float2 g_mlp[4194304];   // MLP output
__device__ __align__(16) float  g_W[8192];        // [4][8][16][16] folded weights
__device__ __align__(16) float  g_Bias[512];      // [4][8][16]     folded biases
// twiddle GEMM A-matrices, tf32-rounded, stored in the mma-paired layout:
//   idx = ((mat*KT + kk)*M + m)*8 + klm*2 + khi,  k = kk*8 + khi*4 + klm
__device__ __align__(16) float  g_Tfwd[4096];     // M=32,K=64 (cos|sin), scale 1/8 baked
__device__ __align__(16) float  g_Tinv[4096];     // M=64,K=32 (cos|sin), scale 1/8 baked

// ---------------- twiddle tables (scalar L stages) ----------------
__constant__ float2 TW32[32] = {
  { 1.000000000f, 0.000000000f},{ 0.980785280f, 0.195090322f},{ 0.923879533f, 0.382683432f},{ 0.831469612f, 0.555570233f},
  { 0.707106781f, 0.707106781f},{ 0.555570233f, 0.831469612f},{ 0.382683432f, 0.923879533f},{ 0.195090322f, 0.980785280f},
  { 0.000000000f, 1.000000000f},{-0.195090322f, 0.980785280f},{-0.382683432f, 0.923879533f},{-0.555570233f, 0.831469612f},
  {-0.707106781f, 0.707106781f},{-0.831469612f, 0.555570233f},{-0.923879533f, 0.382683432f},{-0.980785280f, 0.195090322f},
  {-1.000000000f, 0.000000000f},{-0.980785280f,-0.195090322f},{-0.923879533f,-0.382683432f},{-0.831469612f,-0.555570233f},
  {-0.707106781f,-0.707106781f},{-0.555570233f,-0.831469612f},{-0.382683432f,-0.923879533f},{-0.195090322f,-0.980785280f},
  { 0.000000000f,-1.000000000f},{ 0.195090322f,-0.980785280f},{ 0.382683432f,-0.923879533f},{ 0.555570233f,-0.831469612f},
  { 0.707106781f,-0.707106781f},{ 0.831469612f,-0.555570233f},{ 0.923879533f,-0.382683432f},{ 0.980785280f,-0.195090322f}
};

__device__ __forceinline__ float gelu_f(float v){
  return 0.5f*v*(1.0f+erff(v*0.7071067811865476f));
}

__device__ __forceinline__ float tf32f(float f){
  unsigned u; asm("cvt.rna.tf32.f32 %0, %1;" : "=r"(u) : "f"(f));
  return __uint_as_float(u);
}

__device__ __forceinline__ void mma8(float4& d, float a0, float a1, float a2, float a3,
                                     float b0, float b1){
  asm volatile("mma.sync.aligned.m16n8k8.row.col.f32.tf32.tf32.f32 "
    "{%0,%1,%2,%3}, {%4,%5,%6,%7}, {%8,%9}, {%0,%1,%2,%3};"
    : "+f"(d.x), "+f"(d.y), "+f"(d.z), "+f"(d.w)
    : "r"(__float_as_uint(a0)), "r"(__float_as_uint(a1)),
      "r"(__float_as_uint(a2)), "r"(__float_as_uint(a3)),
      "r"(__float_as_uint(b0)), "r"(__float_as_uint(b1)));
}

// ---------------- K0a: build twiddle GEMM matrices (tiny) ----------------
__global__ void k_init_T(){
  int idx = blockIdx.x*256 + threadIdx.x;   // 8192
  int which = idx >> 12;                    // 0 = fwd, 1 = inv
  int j = idx & 4095;
  int khi = j & 1, klm = (j>>1)&3;
  int m, kk, mat;
  if (which==0){ m=(j>>3)&31; kk=(j>>8)&7;  mat=j>>11; }
  else         { m=(j>>3)&63; kk=(j>>9)&3;  mat=j>>11; }
  int k = kk*8 + khi*4 + klm;
  double t = (double)(m*k)/32.0;            // angle/pi : 2*pi*m*k/64
  double v = (mat ? sinpi(t) : cospi(t)) * 0.125;
  float f = tf32f((float)v);
  if (which==0) g_Tfwd[j] = f; else g_Tinv[j] = f;
}

// ---------------- K0: fold HydraLoRA into dense per-block weights ----------------
__global__ void k_prep(const float* __restrict__ w1, const float* __restrict__ b1,
                       const float* __restrict__ w2, const float* __restrict__ b2,
                       const float* __restrict__ A1r, const float* __restrict__ B1r,
                       const float* __restrict__ A1i, const float* __restrict__ B1i,
                       const float* __restrict__ A2r, const float* __restrict__ B2r,
                       const float* __restrict__ A2i, const float* __restrict__ B2i,
                       const float* __restrict__ ew){
  int k  = blockIdx.x;        // block 0..7
  int io = threadIdx.x;       // 0..255
  int i = io >> 4, o = io & 15;
  float e0 = ew[0], e1 = ew[1], e2 = ew[2], e3 = ew[3];
  const float s = 0.03125f;   // ALPHA/R = 1/32
  const float* Ws[4] = { w1 + k*256, w1 + 2048 + k*256, w2 + k*256, w2 + 2048 + k*256 };
  const float* As[4] = { A1r + k*512, A1i + k*512, A2r + k*512, A2i + k*512 };
  const float* Bs[4] = { B1r + k*2048, B1i + k*2048, B2r + k*2048, B2i + k*2048 };
#pragma unroll
  for (int m = 0; m < 4; m++){
    const float* A  = As[m] + i*32;
    const float* Bb = Bs[m];
    float acc = 0.f;
    for (int r = 0; r < 32; r++){
      float bm = e0*Bb[r*16+o] + e1*Bb[512+r*16+o] + e2*Bb[1024+r*16+o] + e3*Bb[1536+r*16+o];
      acc = fmaf(A[r], bm, acc);
    }
    g_W[((m*8+k)*16+i)*16+o] = Ws[m][i*16+o] + s*acc;
  }
  if (io < 16){
    float b10 = b1[k*16+io], b11 = b1[128+k*16+io];
    float b20 = b2[k*16+io], b21 = b2[128+k*16+io];
    g_Bias[      k*16+io] = b10 - b11;
    g_Bias[128 + k*16+io] = b10 + b11;
    g_Bias[256 + k*16+io] = b20 - b21;
    g_Bias[384 + k*16+io] = b20 + b21;
  }
}

// ---------------- K1: forward rfft over L (32 -> 8 modes), e^{-i} ----------------
__global__ void k_fwd_l(const float* __restrict__ x){
  __shared__ float2 tw[32];
  if (threadIdx.x < 32) tw[threadIdx.x] = TW32[threadIdx.x];
  __syncthreads();
  int site = blockIdx.x;      // b*4096 + y*64 + xx
  int c = threadIdx.x;        // 0..127
  const float* xp = x + (size_t)site*4096 + c;
  float ar[8], ai[8];
#pragma unroll
  for (int l=0;l<8;l++){ ar[l]=0.f; ai[l]=0.f; }
#pragma unroll 4
  for (int t=0;t<32;t++){
    float v = xp[t*128];
#pragma unroll
    for (int l=0;l<8;l++){
      float2 w = tw[(t*l)&31];
      ar[l] = fmaf(v, w.x, ar[l]);
      ai[l] = fmaf(-v, w.y, ai[l]);
    }
  }
  const float s = 0.1767766952966369f; // 1/sqrt(32)
  float2* op = g_s3 + (size_t)site*1024 + c;
#pragma unroll
  for (int l=0;l<8;l++) op[l*128] = make_float2(ar[l]*s, ai[l]*s);
}

// ---------------- generic complex-DFT GEMM stage (tensor cores, tf32) ----------------
// Out[batch][M][2J floats] = T[M][K] (complex, cos|sin) @ In[batch][K][2J floats]
// Per CTA: one batch, one 64-float column tile. 4 warps, each 16 float-cols.
template<int M, int K, int SGN>
__global__ void __launch_bounds__(128) k_dft_mma(const float* __restrict__ in,
                                                 float* __restrict__ out,
                                                 const float* __restrict__ Tg,
                                                 int rowLen2, size_t inStride2,
                                                 size_t outStride2){
  constexpr int KT = K/8;
  constexpr int MT = M/16;
  constexpr int BSLICE = 136;     // 64*2 + 8 pad (klm-slices shift 8 banks -> clean 2-phase LDS.64)
  __shared__ float As[2*M*K];
  __shared__ float Bs[KT*4*BSLICE];
  int tid = threadIdx.x;
  // stage A (global copy of pre-rounded, pre-paired twiddles)
  for (int i = tid; i < 2*M*K/4; i += 128)
    ((float4*)As)[i] = ((const float4*)Tg)[i];
  // stage B: rows k of the input tile, tf32-rounded, paired (k, k+4) layout
  {
    const float* src = in + (size_t)blockIdx.y*inStride2 + blockIdx.x*64;
    for (int i = tid; i < K*16; i += 128){
      int k = i >> 4, c4 = (i & 15)*4;
      float4 v = *(const float4*)(src + (size_t)k*rowLen2 + c4);
      float* d = Bs + ((k>>3)*4 + (k&3))*BSLICE + ((k>>2)&1);
      d[(c4+0)*2] = tf32f(v.x);
      d[(c4+1)*2] = tf32f(v.y);
      d[(c4+2)*2] = tf32f(v.z);
      d[(c4+3)*2] = tf32f(v.w);
    }
  }
  __syncthreads();
  int warp = tid>>5, lane = tid&31;
  int qid = lane>>2, rid = lane&3;    // lane/4, lane%4
  int wcol = warp*16;
  float4 C[2][MT][2];
#pragma unroll
  for (int a=0;a<2;a++)
#pragma unroll
    for (int b=0;b<MT;b++)
#pragma unroll
      for (int c=0;c<2;c++) C[a][b][c] = make_float4(0.f,0.f,0.f,0.f);
#pragma unroll
  for (int kk=0; kk<KT; kk++){
    float2 Bf[2];
#pragma unroll
    for (int nt=0; nt<2; nt++)
      Bf[nt] = *(const float2*)(Bs + (kk*4 + rid)*BSLICE + (wcol + nt*8 + qid)*2);
#pragma unroll
    for (int mm=0; mm<2; mm++){
      const float* Ap = As + (mm*KT + kk)*M*8;
#pragma unroll
      for (int mt=0; mt<MT; mt++){
        float2 a02 = *(const float2*)(Ap + (mt*16+qid)*8 + rid*2);
        float2 a13 = *(const float2*)(Ap + (mt*16+qid+8)*8 + rid*2);
#pragma unroll
        for (int nt=0; nt<2; nt++)
          mma8(C[mm][mt][nt], a02.x, a13.x, a02.y, a13.y, Bf[nt].x, Bf[nt].y);
      }
    }
  }
  // epilogue: combine cos/sin GEMMs into complex outputs, write float2 (re,im)
  float* ob = out + (size_t)blockIdx.y*outStride2 + blockIdx.x*64;
#pragma unroll
  for (int mt=0; mt<MT; mt++){
#pragma unroll
    for (int nt=0; nt<2; nt++){
      float4 cr = C[0][mt][nt], ci = C[1][mt][nt];
      int col = wcol + nt*8 + rid*2;
      int m0 = mt*16 + qid;
      float2 v0, v1;
      if (SGN > 0){ // forward e^{-i}: Xr = C@Vr + S@Vi ; Xi = C@Vi - S@Vr
        v0 = make_float2(cr.x + ci.y, cr.y - ci.x);
        v1 = make_float2(cr.z + ci.w, cr.w - ci.z);
      } else {      // inverse e^{+i}: Xr = C@Vr - S@Vi ; Xi = C@Vi + S@Vr
        v0 = make_float2(cr.x - ci.y, cr.y + ci.x);
        v1 = make_float2(cr.z - ci.w, cr.w + ci.z);
      }
      *(float2*)(ob + (size_t)m0*rowLen2 + col) = v0;
      *(float2*)(ob + (size_t)(m0+8)*rowLen2 + col) = v1;
    }
  }
}

// ---------------- K4: complex block-diagonal 2-layer MLP (LoRA folded) ----------------
__global__ void k_mlp(){
  __shared__ float sW[32*257];
  __shared__ float sB[32*17];
  for (int i=threadIdx.x; i<8192; i+=256) sW[(i>>8)*257 + (i&255)] = g_W[i];
  for (int i=threadIdx.x; i<512;  i+=256) sB[(i>>4)*17  + (i&15) ] = g_Bias[i];
  __syncthreads();
  int tid = blockIdx.x*256 + threadIdx.x;   // 262144 = 32768 sites * 8 blocks
  int nb = tid & 7;
  int site = tid >> 3;
  const float2* ip = g_spec + (size_t)site*128 + nb*16;
  const float* W1R = sW + nb*257;
  const float* W1I = sW + (8+nb)*257;
  const float* W2R = sW + (16+nb)*257;
  const float* W2I = sW + (24+nb)*257;
  const float* B0 = sB + nb*17;
  const float* B1 = sB + (8+nb)*17;
  const float* B2 = sB + (16+nb)*17;
  const float* B3 = sB + (24+nb)*17;
  float xr[16], xi[16];
#pragma unroll
  for (int i=0;i<16;i++){ float2 v = ip[i]; xr[i]=v.x; xi[i]=v.y; }
  float pr[16], pi[16];
#pragma unroll
  for (int o=0;o<16;o++){ pr[o]=B0[o]; pi[o]=B1[o]; }
#pragma unroll
  for (int i=0;i<16;i++){
#pragma unroll
    for (int o=0;o<16;o++){
      float wr = W1R[i*16+o], wi = W1I[i*16+o];
      pr[o] += xr[i]*wr - xi[i]*wi;
      pi[o] += xi[i]*wr + xr[i]*wi;
    }
  }
#pragma unroll
  for (int o=0;o<16;o++){ pr[o]=gelu_f(pr[o]); pi[o]=gelu_f(pi[o]); }
  float qr[16], qi[16];
#pragma unroll
  for (int o=0;o<16;o++){ qr[o]=B2[o]; qi[o]=B3[o]; }
#pragma unroll
  for (int i=0;i<16;i++){
#pragma unroll
    for (int o=0;o<16;o++){
      float wr = W2R[i*16+o], wi = W2I[i*16+o];
      qr[o] += pr[i]*wr - pi[i]*wi;
      qi[o] += pi[i]*wr + pr[i]*wi;
    }
  }
  float2* op = g_mlp + (size_t)site*128 + nb*16;
#pragma unroll
  for (int o=0;o<16;o++) op[o] = make_float2(qr[o], qi[o]);
}

// ---------------- K7: inverse rfft over L (8 modes -> 32 real) + residual ----------------
__global__ void k_inv_l(const float* __restrict__ xin, float* __restrict__ out){
  __shared__ float2 tw[32];
  if (threadIdx.x < 32) tw[threadIdx.x] = TW32[threadIdx.x];
  __syncthreads();
  int tid = blockIdx.x*blockDim.x + threadIdx.x;  // 2097152
  int c = tid & 127;
  int site = tid >> 7;                            // b*4096 + y*64 + x
  const float2* ip = g_s3 + (size_t)site*1024 + c;
  float Xr[8], Xi[8];
#pragma unroll
  for (int l=0;l<8;l++){ float2 v = ip[l*128]; Xr[l]=v.x; Xi[l]=v.y; }
#pragma unroll
  for (int l=1;l<8;l++){ Xr[l]*=2.f; Xi[l]*=2.f; }
  const float s = 0.1767766952966369f; // 1/sqrt(32)
  const float* rp = xin + (size_t)site*4096 + c;
  float* op = out + (size_t)site*4096 + c;
#pragma unroll 4
  for (int t=0;t<32;t++){
    float v = Xr[0];
#pragma unroll
    for (int l=1;l<8;l++){
      float2 w = tw[(l*t)&31];
      v += Xr[l]*w.x - Xi[l]*w.y;
    }
    op[t*128] = fmaf(v, s, rp[t*128]);
  }
}

// ---------------- launch ----------------
extern "C" void kernel_launch(void* const* d_in, const int* in_sizes, int n_in,
                              void* d_out, int out_size){
  (void)in_sizes; (void)n_in; (void)out_size;
  const float* x = (const float*)d_in[0];
  void *ps3, *ps2, *pspec, *pmlp, *ptf, *pti;
  cudaGetSymbolAddress(&ps3,   g_s3);
  cudaGetSymbolAddress(&ps2,   g_s2);
  cudaGetSymbolAddress(&pspec, g_spec);
  cudaGetSymbolAddress(&pmlp,  g_mlp);
  cudaGetSymbolAddress(&ptf,   g_Tfwd);
  cudaGetSymbolAddress(&pti,   g_Tinv);
  const float* s3 = (const float*)ps3;
  const float* s2 = (const float*)ps2;
  const float* spec = (const float*)pspec;
  const float* mlp = (const float*)pmlp;
  const float* tf = (const float*)ptf;
  const float* ti = (const float*)pti;

  k_prep<<<8,256>>>((const float*)d_in[1], (const float*)d_in[2], (const float*)d_in[3],
                    (const float*)d_in[4], (const float*)d_in[5], (const float*)d_in[6],
                    (const float*)d_in[7], (const float*)d_in[8], (const float*)d_in[9],
                    (const float*)d_in[10], (const float*)d_in[11], (const float*)d_in[12],
                    (const float*)d_in[13]);
  k_init_T<<<32,256>>>();
  k_fwd_l<<<16384,128>>>(x);
  // fwd W: [bh=256] batches, Out[32][1024c] = T @ In[64][1024c]
  k_dft_mma<32,64, 1><<<dim3(32,256),128>>>(s3, (float*)s2, tf, 2048, 131072, 65536);
  // fwd H: [b=4] batches, Out[32][32768c] = T @ In[64][32768c]
  k_dft_mma<32,64, 1><<<dim3(1024,4),128>>>(s2, (float*)spec, tf, 65536, 4194304, 2097152);
  k_mlp<<<1024,256>>>();
  // inv H: [b=4] batches, Out[64][32768c] = T @ In[32][32768c]
  k_dft_mma<64,32,-1><<<dim3(1024,4),128>>>(mlp, (float*)s2, ti, 65536, 2097152, 4194304);
  // inv W: [by=256] batches, Out[64][1024c] = T @ In[32][1024c]
  k_dft_mma<64,32,-1><<<dim3(32,256),128>>>(s2, (float*)s3, ti, 2048, 65536, 131072);
  k_inv_l<<<16384,128>>>(x, (float*)d_out);
}

// round 4
// speedup vs baseline: 1.6645x; 1.0007x over previous
#include <cuda_runtime.h>
#include <math.h>

// ---------------- scratch (device globals; no runtime allocation) ----------------
__device__ __align__(16) float2 g_s3[16777216];   // [4][64][64][8][128]  (fwd L out / inv W out)
__device__ __align__(16) float2 g_s2[8388608];    // [4][64][32][8][128]  (fwd W out / inv H out)
__device__ __align__(16) float2 g_spec[4194304];  // [4][32][32][8][128]  truncated spectrum
__device__ __align__(16) float2 g_mlp[4194304];   // MLP output
__device__ __align__(16) float  g_W[8192];        // [4][8][16][16] folded weights
__device__ __align__(16) float  g_Bias[512];      // [4][8][16]     folded biases
// twiddle GEMM A-matrices, tf32-rounded, stored in the mma-paired layout:
//   idx = ((mat*KT + kk)*M + m)*8 + klm*2 + khi,  k = kk*8 + khi*4 + klm
__device__ __align__(16) float  g_Tfwd[4096];     // M=32,K=64 (cos|sin), scale 1/8 baked
__device__ __align__(16) float  g_Tinv[4096];     // M=64,K=32 (cos|sin), scale 1/8 baked

// ---------------- twiddle tables (scalar L stages) ----------------
__constant__ float2 TW32[32] = {
  { 1.000000000f, 0.000000000f},{ 0.980785280f, 0.195090322f},{ 0.923879533f, 0.382683432f},{ 0.831469612f, 0.555570233f},
  { 0.707106781f, 0.707106781f},{ 0.555570233f, 0.831469612f},{ 0.382683432f, 0.923879533f},{ 0.195090322f, 0.980785280f},
  { 0.000000000f, 1.000000000f},{-0.195090322f, 0.980785280f},{-0.382683432f, 0.923879533f},{-0.555570233f, 0.831469612f},
  {-0.707106781f, 0.707106781f},{-0.831469612f, 0.555570233f},{-0.923879533f, 0.382683432f},{-0.980785280f, 0.195090322f},
  {-1.000000000f, 0.000000000f},{-0.980785280f,-0.195090322f},{-0.923879533f,-0.382683432f},{-0.831469612f,-0.555570233f},
  {-0.707106781f,-0.707106781f},{-0.555570233f,-0.831469612f},{-0.382683432f,-0.923879533f},{-0.195090322f,-0.980785280f},
  { 0.000000000f,-1.000000000f},{ 0.195090322f,-0.980785280f},{ 0.382683432f,-0.923879533f},{ 0.555570233f,-0.831469612f},
  { 0.707106781f,-0.707106781f},{ 0.831469612f,-0.555570233f},{ 0.923879533f,-0.382683432f},{ 0.980785280f,-0.195090322f}
};

__device__ __forceinline__ float gelu_f(float v){
  return 0.5f*v*(1.0f+erff(v*0.7071067811865476f));
}

__device__ __forceinline__ float tf32f(float f){
  unsigned u; asm("cvt.rna.tf32.f32 %0, %1;" : "=r"(u) : "f"(f));
  return __uint_as_float(u);
}

__device__ __forceinline__ void mma8(float4& d, float a0, float a1, float a2, float a3,
                                     float b0, float b1){
  asm volatile("mma.sync.aligned.m16n8k8.row.col.f32.tf32.tf32.f32 "
    "{%0,%1,%2,%3}, {%4,%5,%6,%7}, {%8,%9}, {%0,%1,%2,%3};"
    : "+f"(d.x), "+f"(d.y), "+f"(d.z), "+f"(d.w)
    : "r"(__float_as_uint(a0)), "r"(__float_as_uint(a1)),
      "r"(__float_as_uint(a2)), "r"(__float_as_uint(a3)),
      "r"(__float_as_uint(b0)), "r"(__float_as_uint(b1)));
}

// ---------------- K0a: build twiddle GEMM matrices (tiny) ----------------
__global__ void k_init_T(){
  int idx = blockIdx.x*256 + threadIdx.x;   // 8192
  int which = idx >> 12;                    // 0 = fwd, 1 = inv
  int j = idx & 4095;
  int khi = j & 1, klm = (j>>1)&3;
  int m, kk, mat;
  if (which==0){ m=(j>>3)&31; kk=(j>>8)&7;  mat=j>>11; }
  else         { m=(j>>3)&63; kk=(j>>9)&3;  mat=j>>11; }
  int k = kk*8 + khi*4 + klm;
  double t = (double)(m*k)/32.0;            // angle/pi : 2*pi*m*k/64
  double v = (mat ? sinpi(t) : cospi(t)) * 0.125;
  float f = tf32f((float)v);
  if (which==0) g_Tfwd[j] = f; else g_Tinv[j] = f;
}

// ---------------- K0: fold HydraLoRA into dense per-block weights ----------------
__global__ void k_prep(const float* __restrict__ w1, const float* __restrict__ b1,
                       const float* __restrict__ w2, const float* __restrict__ b2,
                       const float* __restrict__ A1r, const float* __restrict__ B1r,
                       const float* __restrict__ A1i, const float* __restrict__ B1i,
                       const float* __restrict__ A2r, const float* __restrict__ B2r,
                       const float* __restrict__ A2i, const float* __restrict__ B2i,
                       const float* __restrict__ ew){
  int k  = blockIdx.x;        // block 0..7
  int io = threadIdx.x;       // 0..255
  int i = io >> 4, o = io & 15;
  float e0 = ew[0], e1 = ew[1], e2 = ew[2], e3 = ew[3];
  const float s = 0.03125f;   // ALPHA/R = 1/32
  const float* Ws[4] = { w1 + k*256, w1 + 2048 + k*256, w2 + k*256, w2 + 2048 + k*256 };
  const float* As[4] = { A1r + k*512, A1i + k*512, A2r + k*512, A2i + k*512 };
  const float* Bs[4] = { B1r + k*2048, B1i + k*2048, B2r + k*2048, B2i + k*2048 };
#pragma unroll
  for (int m = 0; m < 4; m++){
    const float* A  = As[m] + i*32;
    const float* Bb = Bs[m];
    float acc = 0.f;
    for (int r = 0; r < 32; r++){
      float bm = e0*Bb[r*16+o] + e1*Bb[512+r*16+o] + e2*Bb[1024+r*16+o] + e3*Bb[1536+r*16+o];
      acc = fmaf(A[r], bm, acc);
    }
    g_W[((m*8+k)*16+i)*16+o] = Ws[m][i*16+o] + s*acc;
  }
  if (io < 16){
    float b10 = b1[k*16+io], b11 = b1[128+k*16+io];
    float b20 = b2[k*16+io], b21 = b2[128+k*16+io];
    g_Bias[      k*16+io] = b10 - b11;
    g_Bias[128 + k*16+io] = b10 + b11;
    g_Bias[256 + k*16+io] = b20 - b21;
    g_Bias[384 + k*16+io] = b20 + b21;
  }
}

// ---------------- K1: forward rfft over L (32 -> 8 modes), e^{-i} ----------------
__global__ void k_fwd_l(const float* __restrict__ x){
  __shared__ float2 tw[32];
  if (threadIdx.x < 32) tw[threadIdx.x] = TW32[threadIdx.x];
  __syncthreads();
  int site = blockIdx.x;      // b*4096 + y*64 + xx
  int c = threadIdx.x;        // 0..127
  const float* xp = x + (size_t)site*4096 + c;
  float ar[8], ai[8];
#pragma unroll
  for (int l=0;l<8;l++){ ar[l]=0.f; ai[l]=0.f; }
#pragma unroll 4
  for (int t=0;t<32;t++){
    float v = xp[t*128];
#pragma unroll
    for (int l=0;l<8;l++){
      float2 w = tw[(t*l)&31];
      ar[l] = fmaf(v, w.x, ar[l]);
      ai[l] = fmaf(-v, w.y, ai[l]);
    }
  }
  const float s = 0.1767766952966369f; // 1/sqrt(32)
  float2* op = g_s3 + (size_t)site*1024 + c;
#pragma unroll
  for (int l=0;l<8;l++) op[l*128] = make_float2(ar[l]*s, ai[l]*s);
}

// ---------------- generic complex-DFT GEMM stage (tensor cores, tf32) ----------------
// Out[batch][M][2J floats] = T[M][K] (complex, cos|sin) @ In[batch][K][2J floats]
// Per CTA: one batch, one 64-float column tile. 4 warps, each 16 float-cols.
template<int M, int K, int SGN>
__global__ void __launch_bounds__(128) k_dft_mma(const float* __restrict__ in,
                                                 float* __restrict__ out,
                                                 const float* __restrict__ Tg,
                                                 int rowLen2, size_t inStride2,
                                                 size_t outStride2){
  constexpr int KT = K/8;
  constexpr int MT = M/16;
  constexpr int BSLICE = 136;     // 64*2 + 8 pad (klm-slices shift 8 banks -> clean 2-phase LDS.64)
  __shared__ float As[2*M*K];
  __shared__ float Bs[KT*4*BSLICE];
  int tid = threadIdx.x;
  // stage A (global copy of pre-rounded, pre-paired twiddles)
  for (int i = tid; i < 2*M*K/4; i += 128)
    ((float4*)As)[i] = ((const float4*)Tg)[i];
  // stage B: rows k of the input tile, tf32-rounded, paired (k, k+4) layout
  {
    const float* src = in + (size_t)blockIdx.y*inStride2 + blockIdx.x*64;
    for (int i = tid; i < K*16; i += 128){
      int k = i >> 4, c4 = (i & 15)*4;
      float4 v = *(const float4*)(src + (size_t)k*rowLen2 + c4);
      float* d = Bs + ((k>>3)*4 + (k&3))*BSLICE + ((k>>2)&1);
      d[(c4+0)*2] = tf32f(v.x);
      d[(c4+1)*2] = tf32f(v.y);
      d[(c4+2)*2] = tf32f(v.z);
      d[(c4+3)*2] = tf32f(v.w);
    }
  }
  __syncthreads();
  int warp = tid>>5, lane = tid&31;
  int qid = lane>>2, rid = lane&3;    // lane/4, lane%4
  int wcol = warp*16;
  float4 C[2][MT][2];
#pragma unroll
  for (int a=0;a<2;a++)
#pragma unroll
    for (int b=0;b<MT;b++)
#pragma unroll
      for (int c=0;c<2;c++) C[a][b][c] = make_float4(0.f,0.f,0.f,0.f);
#pragma unroll
  for (int kk=0; kk<KT; kk++){
    float2 Bf[2];
#pragma unroll
    for (int nt=0; nt<2; nt++)
      Bf[nt] = *(const float2*)(Bs + (kk*4 + rid)*BSLICE + (wcol + nt*8 + qid)*2);
#pragma unroll
    for (int mm=0; mm<2; mm++){
      const float* Ap = As + (mm*KT + kk)*M*8;
#pragma unroll
      for (int mt=0; mt<MT; mt++){
        float2 a02 = *(const float2*)(Ap + (mt*16+qid)*8 + rid*2);
        float2 a13 = *(const float2*)(Ap + (mt*16+qid+8)*8 + rid*2);
#pragma unroll
        for (int nt=0; nt<2; nt++)
          mma8(C[mm][mt][nt], a02.x, a13.x, a02.y, a13.y, Bf[nt].x, Bf[nt].y);
      }
    }
  }
  // epilogue: combine cos/sin GEMMs into complex outputs, write float2 (re,im)
  float* ob = out + (size_t)blockIdx.y*outStride2 + blockIdx.x*64;
#pragma unroll
  for (int mt=0; mt<MT; mt++){
#pragma unroll
    for (int nt=0; nt<2; nt++){
      float4 cr = C[0][mt][nt], ci = C[1][mt][nt];
      int col = wcol + nt*8 + rid*2;
      int m0 = mt*16 + qid;
      float2 v0, v1;
      if (SGN > 0){ // forward e^{-i}: Xr = C@Vr + S@Vi ; Xi = C@Vi - S@Vr
        v0 = make_float2(cr.x + ci.y, cr.y - ci.x);
        v1 = make_float2(cr.z + ci.w, cr.w - ci.z);
      } else {      // inverse e^{+i}: Xr = C@Vr - S@Vi ; Xi = C@Vi + S@Vr
        v0 = make_float2(cr.x - ci.y, cr.y + ci.x);
        v1 = make_float2(cr.z - ci.w, cr.w + ci.z);
      }
      *(float2*)(ob + (size_t)m0*rowLen2 + col) = v0;
      *(float2*)(ob + (size_t)(m0+8)*rowLen2 + col) = v1;
    }
  }
}

// ---------------- K4: complex block-diagonal 2-layer MLP (LoRA folded) ----------------
__global__ void k_mlp(){
  __shared__ float sW[32*257];
  __shared__ float sB[32*17];
  for (int i=threadIdx.x; i<8192; i+=256) sW[(i>>8)*257 + (i&255)] = g_W[i];
  for (int i=threadIdx.x; i<512;  i+=256) sB[(i>>4)*17  + (i&15) ] = g_Bias[i];
  __syncthreads();
  int tid = blockIdx.x*256 + threadIdx.x;   // 262144 = 32768 sites * 8 blocks
  int nb = tid & 7;
  int site = tid >> 3;
  const float2* ip = g_spec + (size_t)site*128 + nb*16;
  const float* W1R = sW + nb*257;
  const float* W1I = sW + (8+nb)*257;
  const float* W2R = sW + (16+nb)*257;
  const float* W2I = sW + (24+nb)*257;
  const float* B0 = sB + nb*17;
  const float* B1 = sB + (8+nb)*17;
  const float* B2 = sB + (16+nb)*17;
  const float* B3 = sB + (24+nb)*17;
  float xr[16], xi[16];
#pragma unroll
  for (int i=0;i<16;i++){ float2 v = ip[i]; xr[i]=v.x; xi[i]=v.y; }
  float pr[16], pi[16];
#pragma unroll
  for (int o=0;o<16;o++){ pr[o]=B0[o]; pi[o]=B1[o]; }
#pragma unroll
  for (int i=0;i<16;i++){
#pragma unroll
    for (int o=0;o<16;o++){
      float wr = W1R[i*16+o], wi = W1I[i*16+o];
      pr[o] += xr[i]*wr - xi[i]*wi;
      pi[o] += xi[i]*wr + xr[i]*wi;
    }
  }
#pragma unroll
  for (int o=0;o<16;o++){ pr[o]=gelu_f(pr[o]); pi[o]=gelu_f(pi[o]); }
  float qr[16], qi[16];
#pragma unroll
  for (int o=0;o<16;o++){ qr[o]=B2[o]; qi[o]=B3[o]; }
#pragma unroll
  for (int i=0;i<16;i++){
#pragma unroll
    for (int o=0;o<16;o++){
      float wr = W2R[i*16+o], wi = W2I[i*16+o];
      qr[o] += pr[i]*wr - pi[i]*wi;
      qi[o] += pi[i]*wr + pr[i]*wi;
    }
  }
  float2* op = g_mlp + (size_t)site*128 + nb*16;
#pragma unroll
  for (int o=0;o<16;o++) op[o] = make_float2(qr[o], qi[o]);
}

// ---------------- K7: inverse rfft over L (8 modes -> 32 real) + residual ----------------
__global__ void k_inv_l(const float* __restrict__ xin, float* __restrict__ out){
  __shared__ float2 tw[32];
  if (threadIdx.x < 32) tw[threadIdx.x] = TW32[threadIdx.x];
  __syncthreads();
  int tid = blockIdx.x*blockDim.x + threadIdx.x;  // 2097152
  int c = tid & 127;
  int site = tid >> 7;                            // b*4096 + y*64 + x
  const float2* ip = g_s3 + (size_t)site*1024 + c;
  float Xr[8], Xi[8];
#pragma unroll
  for (int l=0;l<8;l++){ float2 v = ip[l*128]; Xr[l]=v.x; Xi[l]=v.y; }
#pragma unroll
  for (int l=1;l<8;l++){ Xr[l]*=2.f; Xi[l]*=2.f; }
  const float s = 0.1767766952966369f; // 1/sqrt(32)
  const float* rp = xin + (size_t)site*4096 + c;
  float* op = out + (size_t)site*4096 + c;
#pragma unroll 4
  for (int t=0;t<32;t++){
    float v = Xr[0];
#pragma unroll
    for (int l=1;l<8;l++){
      float2 w = tw[(l*t)&31];
      v += Xr[l]*w.x - Xi[l]*w.y;
    }
    op[t*128] = fmaf(v, s, rp[t*128]);
  }
}

// ---------------- launch ----------------
extern "C" void kernel_launch(void* const* d_in, const int* in_sizes, int n_in,
                              void* d_out, int out_size){
  (void)in_sizes; (void)n_in; (void)out_size;
  const float* x = (const float*)d_in[0];
  void *ps3, *ps2, *pspec, *pmlp, *ptf, *pti;
  cudaGetSymbolAddress(&ps3,   g_s3);
  cudaGetSymbolAddress(&ps2,   g_s2);
  cudaGetSymbolAddress(&pspec, g_spec);
  cudaGetSymbolAddress(&pmlp,  g_mlp);
  cudaGetSymbolAddress(&ptf,   g_Tfwd);
  cudaGetSymbolAddress(&pti,   g_Tinv);
  const float* s3 = (const float*)ps3;
  const float* s2 = (const float*)ps2;
  const float* spec = (const float*)pspec;
  const float* mlp = (const float*)pmlp;
  const float* tf = (const float*)ptf;
  const float* ti = (const float*)pti;

  k_prep<<<8,256>>>((const float*)d_in[1], (const float*)d_in[2], (const float*)d_in[3],
                    (const float*)d_in[4], (const float*)d_in[5], (const float*)d_in[6],
                    (const float*)d_in[7], (const float*)d_in[8], (const float*)d_in[9],
                    (const float*)d_in[10], (const float*)d_in[11], (const float*)d_in[12],
                    (const float*)d_in[13]);
  k_init_T<<<32,256>>>();
  k_fwd_l<<<16384,128>>>(x);
  // fwd W: [bh=256] batches, Out[32][1024c] = T @ In[64][1024c]
  k_dft_mma<32,64, 1><<<dim3(32,256),128>>>(s3, (float*)s2, tf, 2048, 131072, 65536);
  // fwd H: [b=4] batches, Out[32][32768c] = T @ In[64][32768c]
  k_dft_mma<32,64, 1><<<dim3(1024,4),128>>>(s2, (float*)spec, tf, 65536, 4194304, 2097152);
  k_mlp<<<1024,256>>>();
  // inv H: [b=4] batches, Out[64][32768c] = T @ In[32][32768c]
  k_dft_mma<64,32,-1><<<dim3(1024,4),128>>>(mlp, (float*)s2, ti, 65536, 2097152, 4194304);
  // inv W: [by=256] batches, Out[64][1024c] = T @ In[32][1024c]
  k_dft_mma<64,32,-1><<<dim3(32,256),128>>>(s2, (float*)s3, ti, 2048, 65536, 131072);
  k_inv_l<<<16384,128>>>(x, (float*)d_out);
}